// round 1
// baseline (speedup 1.0000x reference)
#include <cuda_runtime.h>
#include <math.h>

#define BATCH 2
#define HWd   192
#define HW2   (HWd*HWd)      // 36864
#define HGd   48
#define Ntok  (HGd*HGd)      // 2304
#define D2    256
#define VDdim 2048
#define NFtot 3
#define LISTCAP 128

// ---------------- scratch (device globals; no allocs allowed) ----------------
__device__ float g_buf1[(size_t)BATCH*384*HW2];   // 1x1 conv out: ch0..255 = qk, 256..383 = v
__device__ float g_buf2[(size_t)BATCH*384*HW2];   // after dw3x3
__device__ float g_buf3[(size_t)BATCH*512*HW2];   // ch0..255 = q2(1x1), 256..511 = k2(1x1)
__device__ float g_buf4[(size_t)BATCH*512*Ntok];  // after dw4x4 stride4  [b][ch][token]
__device__ float g_qtok[(size_t)BATCH*Ntok*D2];   // normalized q, token-major
__device__ float g_attn[(size_t)BATCH*NFtot*Ntok*Ntok];
__device__ float g_otok[(size_t)BATCH*NFtot*Ntok*VDdim];

// ---------------- generic SGEMM (A[M,K] row-major weights, B[K,N], C[M,N]) ---
__global__ void __launch_bounds__(256) sgemm_nn(
    const float* __restrict__ A, const float* __restrict__ B,
    const float* __restrict__ bias, float* __restrict__ C,
    int K, long bStride, long cStride, int ldb, int ldc)
{
    const float* Bp = B + (long)blockIdx.z * bStride;
    float*       Cp = C + (long)blockIdx.z * cStride;
    int n0 = blockIdx.x * 64;
    int m0 = blockIdx.y * 64;
    int tid = threadIdx.x;
    int tx = tid & 15, ty = tid >> 4;

    __shared__ float As[16][64];
    __shared__ float Bs[16][68];
    float acc[4][4] = {};

    int arow = tid >> 2, akq = (tid & 3) * 4;
    int bkk  = tid >> 4, bcq = (tid & 15) * 4;

    for (int k0 = 0; k0 < K; k0 += 16) {
        float4 a4 = *reinterpret_cast<const float4*>(&A[(long)(m0 + arow) * K + k0 + akq]);
        As[akq+0][arow] = a4.x; As[akq+1][arow] = a4.y;
        As[akq+2][arow] = a4.z; As[akq+3][arow] = a4.w;
        float4 b4 = *reinterpret_cast<const float4*>(&Bp[(long)(k0 + bkk) * ldb + n0 + bcq]);
        *reinterpret_cast<float4*>(&Bs[bkk][bcq]) = b4;
        __syncthreads();
        #pragma unroll
        for (int kk = 0; kk < 16; kk++) {
            float a[4], bb[4];
            #pragma unroll
            for (int i = 0; i < 4; i++) a[i]  = As[kk][ty*4+i];
            #pragma unroll
            for (int j = 0; j < 4; j++) bb[j] = Bs[kk][tx*4+j];
            #pragma unroll
            for (int i = 0; i < 4; i++)
                #pragma unroll
                for (int j = 0; j < 4; j++)
                    acc[i][j] += a[i] * bb[j];
        }
        __syncthreads();
    }
    #pragma unroll
    for (int i = 0; i < 4; i++) {
        float bv = bias ? bias[m0 + ty*4 + i] : 0.f;
        #pragma unroll
        for (int j = 0; j < 4; j++)
            Cp[(long)(m0 + ty*4 + i) * ldc + n0 + tx*4 + j] = acc[i][j] + bv;
    }
}

// ---------------- depthwise 3x3 pad1 (on g_buf1 -> g_buf2) -------------------
__global__ void dw3x3(const float* __restrict__ qk_dw_w, const float* __restrict__ qk_dw_b,
                      const float* __restrict__ v_dw_w,  const float* __restrict__ v_dw_b)
{
    int idx = blockIdx.x * 256 + threadIdx.x;
    if (idx >= BATCH*384*HW2) return;
    int p  = idx % HW2;
    int ch = (idx / HW2) % 384;
    int b  = idx / (384*HW2);
    int h = p / HWd, w = p % HWd;
    const float* wgt; float bv;
    if (ch < 256) { wgt = qk_dw_w + ch*9;        bv = qk_dw_b[ch]; }
    else          { wgt = v_dw_w  + (ch-256)*9;  bv = v_dw_b[ch-256]; }
    const float* in = g_buf1 + ((long)(b*384 + ch)) * HW2;
    float s = bv;
    #pragma unroll
    for (int ky = 0; ky < 3; ky++) {
        int y = h + ky - 1;
        if ((unsigned)y >= (unsigned)HWd) continue;
        #pragma unroll
        for (int kx = 0; kx < 3; kx++) {
            int x = w + kx - 1;
            if ((unsigned)x >= (unsigned)HWd) continue;
            s += wgt[ky*3+kx] * in[y*HWd + x];
        }
    }
    g_buf2[idx] = s;
}

// ---------------- depthwise 4x4 stride4 pad1 (g_buf3 -> g_buf4) --------------
__global__ void dw4x4(const float* __restrict__ q2_dw_w, const float* __restrict__ q2_dw_b,
                      const float* __restrict__ k2_dw_w, const float* __restrict__ k2_dw_b)
{
    int idx = blockIdx.x * 256 + threadIdx.x;
    if (idx >= BATCH*512*Ntok) return;
    int t  = idx % Ntok;
    int ch = (idx / Ntok) % 512;
    int b  = idx / (512*Ntok);
    int oy = t / HGd, ox = t % HGd;
    const float* wgt; float bv;
    if (ch < 256) { wgt = q2_dw_w + ch*16;       bv = q2_dw_b[ch]; }
    else          { wgt = k2_dw_w + (ch-256)*16; bv = k2_dw_b[ch-256]; }
    const float* in = g_buf3 + ((long)(b*512 + ch)) * HW2;
    float s = bv;
    #pragma unroll
    for (int ky = 0; ky < 4; ky++) {
        int y = oy*4 - 1 + ky;
        if ((unsigned)y >= (unsigned)HWd) continue;
        #pragma unroll
        for (int kx = 0; kx < 4; kx++) {
            int x = ox*4 - 1 + kx;
            if ((unsigned)x >= (unsigned)HWd) continue;
            s += wgt[ky*4+kx] * in[y*HWd + x];
        }
    }
    g_buf4[idx] = s;
}

// ---------------- l2 normalize + token-major q/k -----------------------------
__global__ void __launch_bounds__(256) norm_qk(float* __restrict__ kout)
{
    int token = blockIdx.x, b = blockIdx.y, d = threadIdx.x;
    float qv = g_buf4[((long)b*512 + d)       * Ntok + token];
    float kv = g_buf4[((long)b*512 + 256 + d) * Ntok + token];
    __shared__ float red[256];
    __shared__ float qinv_s, kinv_s;
    red[d] = qv*qv; __syncthreads();
    for (int s = 128; s > 0; s >>= 1) { if (d < s) red[d] += red[d+s]; __syncthreads(); }
    if (d == 0) qinv_s = 1.f / fmaxf(sqrtf(red[0]), 1e-12f);
    __syncthreads();
    red[d] = kv*kv; __syncthreads();
    for (int s = 128; s > 0; s >>= 1) { if (d < s) red[d] += red[d+s]; __syncthreads(); }
    if (d == 0) kinv_s = 1.f / fmaxf(sqrtf(red[0]), 1e-12f);
    __syncthreads();
    g_qtok[((long)b*Ntok + token) * D2 + d] = qv * qinv_s;
    kout  [((long)(b*2 + 1)*Ntok + token) * D2 + d] = kv * kinv_s;
}

// ---------------- build v_new (strided-window permute) into d_out ------------
__global__ void build_vnew(float* __restrict__ vout)
{
    int idx = blockIdx.x * 256 + threadIdx.x;
    if (idx >= BATCH*Ntok*VDdim) return;
    int vd    = idx % VDdim;
    int token = (idx / VDdim) % Ntok;
    int b     = idx / (Ntok*VDdim);
    int c  = vd & 127;
    int p2 = (vd >> 7) & 3;
    int p1 = vd >> 9;
    int hi = token / HGd, wi = token % HGd;
    float val = g_buf2[((long)(b*384 + 256 + c)) * HW2 + (p1*HGd + hi) * HWd + (p2*HGd + wi)];
    vout[((long)(b*2 + 1)*Ntok + token) * VDdim + vd] = val;
}

// ---------------- attention GEMM: attn = (Q . K^T) * temp --------------------
__global__ void __launch_bounds__(256) attn_gemm(
    const float* __restrict__ kc, const float* __restrict__ knew,
    const float* __restrict__ temp)
{
    int z = blockIdx.z; int b = z / NFtot, f = z % NFtot;
    const float* Qp = g_qtok + (long)b * Ntok * D2;
    const float* Kp = (f < 2) ? (kc   + ((long)(b*2 + f)) * Ntok * D2)
                              : (knew + ((long)(b*2 + 1)) * Ntok * D2);
    int m0 = blockIdx.x * 64, n0 = blockIdx.y * 64;
    int tid = threadIdx.x, tx = tid & 15, ty = tid >> 4;
    __shared__ float As[16][64];
    __shared__ float Bs[16][68];
    float acc[4][4] = {};
    int row = tid >> 2, kq = (tid & 3) * 4;
    for (int k0 = 0; k0 < D2; k0 += 16) {
        float4 a4 = *reinterpret_cast<const float4*>(&Qp[(long)(n0 + row) * D2 + k0 + kq]);
        As[kq+0][row] = a4.x; As[kq+1][row] = a4.y; As[kq+2][row] = a4.z; As[kq+3][row] = a4.w;
        float4 b4 = *reinterpret_cast<const float4*>(&Kp[(long)(m0 + row) * D2 + k0 + kq]);
        Bs[kq+0][row] = b4.x; Bs[kq+1][row] = b4.y; Bs[kq+2][row] = b4.z; Bs[kq+3][row] = b4.w;
        __syncthreads();
        #pragma unroll
        for (int kk = 0; kk < 16; kk++) {
            float a[4], bb[4];
            #pragma unroll
            for (int i = 0; i < 4; i++) a[i]  = As[kk][ty*4+i];
            #pragma unroll
            for (int j = 0; j < 4; j++) bb[j] = Bs[kk][tx*4+j];
            #pragma unroll
            for (int i = 0; i < 4; i++)
                #pragma unroll
                for (int j = 0; j < 4; j++)
                    acc[i][j] += a[i] * bb[j];
        }
        __syncthreads();
    }
    float ts = *temp;
    float* Cp = g_attn + (long)z * Ntok * Ntok;
    #pragma unroll
    for (int i = 0; i < 4; i++)
        #pragma unroll
        for (int j = 0; j < 4; j++)
            Cp[(long)(n0 + ty*4 + i) * Ntok + m0 + tx*4 + j] = acc[i][j] * ts;
}

// ---------------- top-k + local-mask sparse softmax + sparse AV --------------
__global__ void __launch_bounds__(256) sparse_attn_av(
    const float* __restrict__ v_cached, const float* __restrict__ vout)
{
    int n = blockIdx.x, f = blockIdx.y, b = blockIdx.z;
    const float* arow = g_attn + ((long)(b*NFtot + f) * Ntok + n) * Ntok;
    int tid = threadIdx.x;

    // pass 1: per-thread top-5
    float t5[5] = {-INFINITY,-INFINITY,-INFINITY,-INFINITY,-INFINITY};
    for (int m = tid; m < Ntok; m += 256) {
        float v = arow[m];
        if (v > t5[4]) {
            t5[4] = v;
            #pragma unroll
            for (int i = 4; i > 0; i--)
                if (t5[i] > t5[i-1]) { float tmp = t5[i-1]; t5[i-1] = t5[i]; t5[i] = tmp; }
        }
    }
    __shared__ float cand[256*5];
    __shared__ float red[256];
    #pragma unroll
    for (int i = 0; i < 5; i++) cand[tid*5 + i] = t5[i];
    __syncthreads();

    // 5 rounds of max-with-exclusion -> kth largest
    float thr = INFINITY;
    for (int r = 0; r < 5; r++) {
        float lm = -INFINITY;
        #pragma unroll
        for (int i = 0; i < 5; i++) {
            float v = cand[tid*5 + i];
            if (v < thr && v > lm) lm = v;
        }
        red[tid] = lm; __syncthreads();
        for (int s = 128; s > 0; s >>= 1) { if (tid < s) red[tid] = fmaxf(red[tid], red[tid+s]); __syncthreads(); }
        thr = red[0];
        __syncthreads();
    }
    float kth = thr;

    // pass 2: collect nonzero entries of attn*(1[>=kth] + 1[local])
    __shared__ int   nnz;
    __shared__ int   sidx[LISTCAP];
    __shared__ float sval[LISTCAP];
    if (tid == 0) nnz = 0;
    __syncthreads();
    int ny = n / HGd, nx = n % HGd;
    for (int m = tid; m < Ntok; m += 256) {
        float a = arow[m];
        float coef = (a >= kth) ? 1.f : 0.f;
        int my = m / HGd, mx = m % HGd;
        if (abs(ny - my) + abs(nx - mx) <= 4) coef += 1.f;
        float v = a * coef;
        if (v != 0.f) {
            int pos = atomicAdd(&nnz, 1);
            if (pos < LISTCAP) { sidx[pos] = m; sval[pos] = v; }
        }
    }
    __syncthreads();
    int cnt = min(nnz, LISTCAP);

    // softmax over the sparse list
    __shared__ float smax, ssum;
    if (tid == 0) {
        float mx = -INFINITY;
        for (int e = 0; e < cnt; e++) mx = fmaxf(mx, sval[e]);
        smax = mx;
    }
    __syncthreads();
    if (tid < cnt) sval[tid] = expf(sval[tid] - smax);
    __syncthreads();
    if (tid == 0) {
        float s = 0.f;
        for (int e = 0; e < cnt; e++) s += sval[e];
        ssum = s;
    }
    __syncthreads();
    float inv = 1.f / ssum;

    // sparse AV: each thread owns 8 contiguous vd dims
    const float* vbase = (f < 2) ? (v_cached + ((long)(b*2 + f)) * Ntok * VDdim)
                                 : (vout     + ((long)(b*2 + 1)) * Ntok * VDdim);
    float* orow = g_otok + ((long)(b*NFtot + f) * Ntok + n) * VDdim;
    int d0 = tid * 8;
    float acc[8] = {};
    for (int e = 0; e < cnt; e++) {
        float w = sval[e] * inv;
        const float* vr = vbase + (long)sidx[e] * VDdim + d0;
        float4 v0 = *reinterpret_cast<const float4*>(vr);
        float4 v1 = *reinterpret_cast<const float4*>(vr + 4);
        acc[0] += w*v0.x; acc[1] += w*v0.y; acc[2] += w*v0.z; acc[3] += w*v0.w;
        acc[4] += w*v1.x; acc[5] += w*v1.y; acc[6] += w*v1.z; acc[7] += w*v1.w;
    }
    float4 o0 = {acc[0],acc[1],acc[2],acc[3]};
    float4 o1 = {acc[4],acc[5],acc[6],acc[7]};
    *reinterpret_cast<float4*>(orow + d0)     = o0;
    *reinterpret_cast<float4*>(orow + d0 + 4) = o1;
}

// ---------------- proj 1x1 with fused window de-permute gather ---------------
__global__ void __launch_bounds__(256) proj_gemm(
    const float* __restrict__ W, const float* __restrict__ bias,
    float* __restrict__ Out)
{
    int z  = blockIdx.z;                // b*3+f
    int n0 = blockIdx.x * 64;           // pixel tile
    int m0 = blockIdx.y * 64;           // oc tile
    int tid = threadIdx.x, tx = tid & 15, ty = tid >> 4;
    __shared__ float As[16][64];
    __shared__ float Bs[16][68];
    float acc[4][4] = {};

    int col = tid >> 2, kq = (tid & 3) * 4;
    int p = n0 + col;
    int h = p / HWd, w = p % HWd;
    int token = (h % HGd) * HGd + (w % HGd);
    int vbase = ((h / HGd) * 4 + (w / HGd)) * 128;
    const float* bsrc = g_otok + ((long)z * Ntok + token) * VDdim + vbase + kq;

    for (int k0 = 0; k0 < 128; k0 += 16) {
        float4 a4 = *reinterpret_cast<const float4*>(&W[(long)(m0 + col) * 128 + k0 + kq]);
        As[kq+0][col] = a4.x; As[kq+1][col] = a4.y; As[kq+2][col] = a4.z; As[kq+3][col] = a4.w;
        float4 b4 = *reinterpret_cast<const float4*>(&bsrc[k0]);
        Bs[kq+0][col] = b4.x; Bs[kq+1][col] = b4.y; Bs[kq+2][col] = b4.z; Bs[kq+3][col] = b4.w;
        __syncthreads();
        #pragma unroll
        for (int kk = 0; kk < 16; kk++) {
            float a[4], bb[4];
            #pragma unroll
            for (int i = 0; i < 4; i++) a[i]  = As[kk][ty*4+i];
            #pragma unroll
            for (int j = 0; j < 4; j++) bb[j] = Bs[kk][tx*4+j];
            #pragma unroll
            for (int i = 0; i < 4; i++)
                #pragma unroll
                for (int j = 0; j < 4; j++)
                    acc[i][j] += a[i] * bb[j];
        }
        __syncthreads();
    }
    #pragma unroll
    for (int i = 0; i < 4; i++) {
        float bv = bias[m0 + ty*4 + i];
        #pragma unroll
        for (int j = 0; j < 4; j++)
            Out[((long)z*128 + m0 + ty*4 + i) * HW2 + n0 + tx*4 + j] = acc[i][j] + bv;
    }
}

// ---------------------------------- launch -----------------------------------
extern "C" void kernel_launch(void* const* d_in, const int* in_sizes, int n_in,
                              void* d_out, int out_size)
{
    (void)in_sizes; (void)n_in; (void)out_size;
    const float* x         = (const float*)d_in[0];
    const float* k_cached  = (const float*)d_in[1];
    const float* v_cached  = (const float*)d_in[2];
    const float* temperature = (const float*)d_in[3];
    const float* qk_w  = (const float*)d_in[4],  *qk_b  = (const float*)d_in[5];
    const float* qk_dw_w = (const float*)d_in[6], *qk_dw_b = (const float*)d_in[7];
    const float* v_w   = (const float*)d_in[8],  *v_b   = (const float*)d_in[9];
    const float* v_dw_w = (const float*)d_in[10], *v_dw_b = (const float*)d_in[11];
    const float* k2_w  = (const float*)d_in[12], *k2_b  = (const float*)d_in[13];
    const float* k2_dw_w = (const float*)d_in[14], *k2_dw_b = (const float*)d_in[15];
    const float* q2_w  = (const float*)d_in[16], *q2_b  = (const float*)d_in[17];
    const float* q2_dw_w = (const float*)d_in[18], *q2_dw_b = (const float*)d_in[19];
    const float* proj_w = (const float*)d_in[20], *proj_b = (const float*)d_in[21];

    float* out = (float*)d_out;
    const long OUT_K = (long)BATCH * NFtot * 128 * HW2;           // 28,311,552
    const long OUT_V = OUT_K + (long)BATCH * 2 * Ntok * D2;       // +2,359,296
    float* kout = out + OUT_K;
    float* vout = out + OUT_V;

    void* p;
    cudaGetSymbolAddress(&p, g_buf1); float* buf1 = (float*)p;
    cudaGetSymbolAddress(&p, g_buf2); float* buf2 = (float*)p;
    cudaGetSymbolAddress(&p, g_buf3); float* buf3 = (float*)p;

    dim3 blk(256);

    // stage A: 1x1 convs from x (qk: 256ch, v: 128ch)
    sgemm_nn<<<dim3(576,4,BATCH), blk>>>(qk_w, x, qk_b, buf1,
                                         128, (long)128*HW2, (long)384*HW2, HW2, HW2);
    sgemm_nn<<<dim3(576,2,BATCH), blk>>>(v_w, x, v_b, buf1 + (long)256*HW2,
                                         128, (long)128*HW2, (long)384*HW2, HW2, HW2);
    // stage B: depthwise 3x3 pad1 on all 384 channels
    dw3x3<<<(BATCH*384*HW2 + 255)/256, blk>>>(qk_dw_w, qk_dw_b, v_dw_w, v_dw_b);
    // stage C: 1x1 convs q2 (from q half) and k2 (from k half)
    sgemm_nn<<<dim3(576,4,BATCH), blk>>>(q2_w, buf2, q2_b, buf3,
                                         128, (long)384*HW2, (long)512*HW2, HW2, HW2);
    sgemm_nn<<<dim3(576,4,BATCH), blk>>>(k2_w, buf2 + (long)128*HW2, k2_b, buf3 + (long)256*HW2,
                                         128, (long)384*HW2, (long)512*HW2, HW2, HW2);
    // stage D: depthwise 4x4 stride4 pad1 -> 48x48 token grid
    dw4x4<<<(BATCH*512*Ntok + 255)/256, blk>>>(q2_dw_w, q2_dw_b, k2_dw_w, k2_dw_b);
    // stage E: l2-normalize q/k, token-major; k_new straight into d_out
    norm_qk<<<dim3(Ntok, BATCH), blk>>>(kout);
    // stage F: v_new window permute straight into d_out
    build_vnew<<<(BATCH*Ntok*VDdim + 255)/256, blk>>>(vout);
    // cached slices -> output slots f'=0
    for (int b = 0; b < BATCH; b++) {
        cudaMemcpyAsync(kout + (long)(b*2)*Ntok*D2,
                        k_cached + (long)(b*2+1)*Ntok*D2,
                        (size_t)Ntok*D2*sizeof(float), cudaMemcpyDeviceToDevice, 0);
        cudaMemcpyAsync(vout + (long)(b*2)*Ntok*VDdim,
                        v_cached + (long)(b*2+1)*Ntok*VDdim,
                        (size_t)Ntok*VDdim*sizeof(float), cudaMemcpyDeviceToDevice, 0);
    }
    // stage G: attention logits (6 GEMMs via grid.z)
    attn_gemm<<<dim3(36,36,BATCH*NFtot), blk>>>(k_cached, kout, temperature);
    // stage H: top-k + local mask sparse softmax + sparse AV
    sparse_attn_av<<<dim3(Ntok, NFtot, BATCH), blk>>>(v_cached, vout);
    // stage I: proj 1x1 with fused de-permute, writes final out
    proj_gemm<<<dim3(576,2,BATCH*NFtot), blk>>>(proj_w, proj_b, out);
}

// round 2
// speedup vs baseline: 1.2317x; 1.2317x over previous
#include <cuda_runtime.h>
#include <math.h>

#define BATCH 2
#define HWd   192
#define HW2   (HWd*HWd)      // 36864
#define HGd   48
#define Ntok  (HGd*HGd)      // 2304
#define D2    256
#define VDdim 2048
#define NFtot 3
#define LISTCAP 128

// ---------------- scratch (device globals; no allocs allowed) ----------------
__device__ float g_buf1[(size_t)BATCH*384*HW2];   // 1x1 conv out: ch0..255 = qk, 256..383 = v
__device__ float g_buf2[(size_t)BATCH*384*HW2];   // after dw3x3
__device__ float g_buf3[(size_t)BATCH*512*HW2];   // ch0..255 = q2(1x1), 256..511 = k2(1x1)
__device__ float g_buf4[(size_t)BATCH*512*Ntok];  // after dw4x4 stride4  [b][ch][token]
__device__ float g_qtok[(size_t)BATCH*Ntok*D2];   // normalized q * temperature, token-major
__device__ float g_attn[(size_t)BATCH*NFtot*Ntok*Ntok];
__device__ float g_otok[(size_t)BATCH*NFtot*Ntok*VDdim];

// =============================================================================
// Conv-style SGEMM: C[M,N] = A[M,K] (K-contig) * B[K,N] (N-contig) + bias
// 128x128 tile, 8x8/thread, KTILE=16
// =============================================================================
__global__ void __launch_bounds__(256) sgemm_conv(
    const float* __restrict__ A, const float* __restrict__ B,
    const float* __restrict__ bias, float* __restrict__ C,
    int K, long bStride, long cStride, int ldb, int ldc)
{
    const float* Bp = B + (long)blockIdx.z * bStride;
    float*       Cp = C + (long)blockIdx.z * cStride;
    int n0 = blockIdx.x * 128, m0 = blockIdx.y * 128;
    int t = threadIdx.x;
    int tx = t & 15, ty = t >> 4;
    __shared__ float As[16][132];
    __shared__ float Bs[16][128];
    float acc[8][8] = {};
    int arow = t >> 1, akq = (t & 1) * 8;
    int bk = t >> 4, bn = (t & 15) * 4;
    const float* Ap = A + (long)(m0 + arow) * K + akq;

    for (int k0 = 0; k0 < K; k0 += 16) {
        float4 a0 = *(const float4*)(Ap + k0);
        float4 a1 = *(const float4*)(Ap + k0 + 4);
        const float* bsrc = Bp + (long)(k0 + bk) * ldb + n0;
        float4 b0 = *(const float4*)(bsrc + bn);
        float4 b1 = *(const float4*)(bsrc + bn + 64);
        __syncthreads();
        As[akq+0][arow]=a0.x; As[akq+1][arow]=a0.y; As[akq+2][arow]=a0.z; As[akq+3][arow]=a0.w;
        As[akq+4][arow]=a1.x; As[akq+5][arow]=a1.y; As[akq+6][arow]=a1.z; As[akq+7][arow]=a1.w;
        *(float4*)&Bs[bk][bn]      = b0;
        *(float4*)&Bs[bk][bn+64]   = b1;
        __syncthreads();
        #pragma unroll
        for (int kk = 0; kk < 16; kk++) {
            float4 av0 = *(const float4*)&As[kk][ty*4];
            float4 av1 = *(const float4*)&As[kk][64+ty*4];
            float4 bv0 = *(const float4*)&Bs[kk][tx*4];
            float4 bv1 = *(const float4*)&Bs[kk][64+tx*4];
            float a8[8] = {av0.x,av0.y,av0.z,av0.w,av1.x,av1.y,av1.z,av1.w};
            float b8[8] = {bv0.x,bv0.y,bv0.z,bv0.w,bv1.x,bv1.y,bv1.z,bv1.w};
            #pragma unroll
            for (int i = 0; i < 8; i++)
                #pragma unroll
                for (int j = 0; j < 8; j++)
                    acc[i][j] += a8[i] * b8[j];
        }
    }
    #pragma unroll
    for (int i = 0; i < 8; i++) {
        int m = (i < 4) ? (ty*4 + i) : (64 + ty*4 + i - 4);
        float bv = bias ? bias[m0 + m] : 0.f;
        float4 o0 = {acc[i][0]+bv, acc[i][1]+bv, acc[i][2]+bv, acc[i][3]+bv};
        float4 o1 = {acc[i][4]+bv, acc[i][5]+bv, acc[i][6]+bv, acc[i][7]+bv};
        *(float4*)&Cp[(long)(m0+m)*ldc + n0 + tx*4]      = o0;
        *(float4*)&Cp[(long)(m0+m)*ldc + n0 + 64 + tx*4] = o1;
    }
}

// =============================================================================
// Attention GEMM: attn[query, key] = Q[query,:] . K[key,:]  (temp folded into Q)
// Both operands K-contiguous (token-major).
// =============================================================================
__global__ void __launch_bounds__(256) attn_gemm2(
    const float* __restrict__ kc, const float* __restrict__ knew)
{
    int z = blockIdx.z; int b = z / NFtot, f = z % NFtot;
    const float* Qp = g_qtok + (long)b * Ntok * D2;
    const float* Kp = (f < 2) ? (kc   + ((long)(b*2 + f)) * Ntok * D2)
                              : (knew + ((long)(b*2 + 1)) * Ntok * D2);
    int m0 = blockIdx.y * 128;   // query tile
    int n0 = blockIdx.x * 128;   // key tile
    int t = threadIdx.x;
    int tx = t & 15, ty = t >> 4;
    __shared__ float As[16][132];
    __shared__ float Bs[16][132];
    float acc[8][8] = {};
    int row = t >> 1, kq = (t & 1) * 8;
    const float* Ap = Qp + (long)(m0 + row) * D2 + kq;
    const float* Bp = Kp + (long)(n0 + row) * D2 + kq;

    for (int k0 = 0; k0 < D2; k0 += 16) {
        float4 a0 = *(const float4*)(Ap + k0);
        float4 a1 = *(const float4*)(Ap + k0 + 4);
        float4 b0 = *(const float4*)(Bp + k0);
        float4 b1 = *(const float4*)(Bp + k0 + 4);
        __syncthreads();
        As[kq+0][row]=a0.x; As[kq+1][row]=a0.y; As[kq+2][row]=a0.z; As[kq+3][row]=a0.w;
        As[kq+4][row]=a1.x; As[kq+5][row]=a1.y; As[kq+6][row]=a1.z; As[kq+7][row]=a1.w;
        Bs[kq+0][row]=b0.x; Bs[kq+1][row]=b0.y; Bs[kq+2][row]=b0.z; Bs[kq+3][row]=b0.w;
        Bs[kq+4][row]=b1.x; Bs[kq+5][row]=b1.y; Bs[kq+6][row]=b1.z; Bs[kq+7][row]=b1.w;
        __syncthreads();
        #pragma unroll
        for (int kk = 0; kk < 16; kk++) {
            float4 av0 = *(const float4*)&As[kk][ty*4];
            float4 av1 = *(const float4*)&As[kk][64+ty*4];
            float4 bv0 = *(const float4*)&Bs[kk][tx*4];
            float4 bv1 = *(const float4*)&Bs[kk][64+tx*4];
            float a8[8] = {av0.x,av0.y,av0.z,av0.w,av1.x,av1.y,av1.z,av1.w};
            float b8[8] = {bv0.x,bv0.y,bv0.z,bv0.w,bv1.x,bv1.y,bv1.z,bv1.w};
            #pragma unroll
            for (int i = 0; i < 8; i++)
                #pragma unroll
                for (int j = 0; j < 8; j++)
                    acc[i][j] += a8[i] * b8[j];
        }
    }
    float* Cp = g_attn + (long)z * Ntok * Ntok;
    #pragma unroll
    for (int i = 0; i < 8; i++) {
        int m = (i < 4) ? (ty*4 + i) : (64 + ty*4 + i - 4);
        float4 o0 = {acc[i][0], acc[i][1], acc[i][2], acc[i][3]};
        float4 o1 = {acc[i][4], acc[i][5], acc[i][6], acc[i][7]};
        *(float4*)&Cp[(long)(m0+m)*Ntok + n0 + tx*4]      = o0;
        *(float4*)&Cp[(long)(m0+m)*Ntok + n0 + 64 + tx*4] = o1;
    }
}

// =============================================================================
// proj 1x1 GEMM with fused window de-permute gather (B cols are pixels,
// K=128 contiguous in g_otok per pixel)
// =============================================================================
__global__ void __launch_bounds__(256) proj_gemm2(
    const float* __restrict__ W, const float* __restrict__ bias,
    float* __restrict__ Out)
{
    int z  = blockIdx.z;
    int n0 = blockIdx.x * 128;   // pixel tile
    int t = threadIdx.x;
    int tx = t & 15, ty = t >> 4;
    __shared__ float As[16][132];
    __shared__ float Bs[16][132];
    float acc[8][8] = {};
    int row = t >> 1, kq = (t & 1) * 8;
    const float* Ap = W + (long)row * 128 + kq;
    int p = n0 + row;
    int h = p / HWd, w = p % HWd;
    int token = (h % HGd) * HGd + (w % HGd);
    int vbase = ((h / HGd) * 4 + (w / HGd)) * 128;
    const float* Bp = g_otok + ((long)z * Ntok + token) * VDdim + vbase + kq;

    for (int k0 = 0; k0 < 128; k0 += 16) {
        float4 a0 = *(const float4*)(Ap + k0);
        float4 a1 = *(const float4*)(Ap + k0 + 4);
        float4 b0 = *(const float4*)(Bp + k0);
        float4 b1 = *(const float4*)(Bp + k0 + 4);
        __syncthreads();
        As[kq+0][row]=a0.x; As[kq+1][row]=a0.y; As[kq+2][row]=a0.z; As[kq+3][row]=a0.w;
        As[kq+4][row]=a1.x; As[kq+5][row]=a1.y; As[kq+6][row]=a1.z; As[kq+7][row]=a1.w;
        Bs[kq+0][row]=b0.x; Bs[kq+1][row]=b0.y; Bs[kq+2][row]=b0.z; Bs[kq+3][row]=b0.w;
        Bs[kq+4][row]=b1.x; Bs[kq+5][row]=b1.y; Bs[kq+6][row]=b1.z; Bs[kq+7][row]=b1.w;
        __syncthreads();
        #pragma unroll
        for (int kk = 0; kk < 16; kk++) {
            float4 av0 = *(const float4*)&As[kk][ty*4];
            float4 av1 = *(const float4*)&As[kk][64+ty*4];
            float4 bv0 = *(const float4*)&Bs[kk][tx*4];
            float4 bv1 = *(const float4*)&Bs[kk][64+tx*4];
            float a8[8] = {av0.x,av0.y,av0.z,av0.w,av1.x,av1.y,av1.z,av1.w};
            float b8[8] = {bv0.x,bv0.y,bv0.z,bv0.w,bv1.x,bv1.y,bv1.z,bv1.w};
            #pragma unroll
            for (int i = 0; i < 8; i++)
                #pragma unroll
                for (int j = 0; j < 8; j++)
                    acc[i][j] += a8[i] * b8[j];
        }
    }
    #pragma unroll
    for (int i = 0; i < 8; i++) {
        int m = (i < 4) ? (ty*4 + i) : (64 + ty*4 + i - 4);
        float bv = bias[m];
        float4 o0 = {acc[i][0]+bv, acc[i][1]+bv, acc[i][2]+bv, acc[i][3]+bv};
        float4 o1 = {acc[i][4]+bv, acc[i][5]+bv, acc[i][6]+bv, acc[i][7]+bv};
        *(float4*)&Out[((long)z*128 + m)*HW2 + n0 + tx*4]      = o0;
        *(float4*)&Out[((long)z*128 + m)*HW2 + n0 + 64 + tx*4] = o1;
    }
}

// ---------------- depthwise 3x3 pad1 (on g_buf1 -> g_buf2) -------------------
__global__ void dw3x3(const float* __restrict__ qk_dw_w, const float* __restrict__ qk_dw_b,
                      const float* __restrict__ v_dw_w,  const float* __restrict__ v_dw_b)
{
    int idx = blockIdx.x * 256 + threadIdx.x;
    if (idx >= BATCH*384*HW2) return;
    int p  = idx % HW2;
    int ch = (idx / HW2) % 384;
    int b  = idx / (384*HW2);
    int h = p / HWd, w = p % HWd;
    const float* wgt; float bv;
    if (ch < 256) { wgt = qk_dw_w + ch*9;        bv = qk_dw_b[ch]; }
    else          { wgt = v_dw_w  + (ch-256)*9;  bv = v_dw_b[ch-256]; }
    const float* in = g_buf1 + ((long)(b*384 + ch)) * HW2;
    float s = bv;
    #pragma unroll
    for (int ky = 0; ky < 3; ky++) {
        int y = h + ky - 1;
        if ((unsigned)y >= (unsigned)HWd) continue;
        #pragma unroll
        for (int kx = 0; kx < 3; kx++) {
            int x = w + kx - 1;
            if ((unsigned)x >= (unsigned)HWd) continue;
            s += wgt[ky*3+kx] * in[y*HWd + x];
        }
    }
    g_buf2[idx] = s;
}

// ---------------- depthwise 4x4 stride4 pad1 (g_buf3 -> g_buf4) --------------
__global__ void dw4x4(const float* __restrict__ q2_dw_w, const float* __restrict__ q2_dw_b,
                      const float* __restrict__ k2_dw_w, const float* __restrict__ k2_dw_b)
{
    int idx = blockIdx.x * 256 + threadIdx.x;
    if (idx >= BATCH*512*Ntok) return;
    int t  = idx % Ntok;
    int ch = (idx / Ntok) % 512;
    int b  = idx / (512*Ntok);
    int oy = t / HGd, ox = t % HGd;
    const float* wgt; float bv;
    if (ch < 256) { wgt = q2_dw_w + ch*16;       bv = q2_dw_b[ch]; }
    else          { wgt = k2_dw_w + (ch-256)*16; bv = k2_dw_b[ch-256]; }
    const float* in = g_buf3 + ((long)(b*512 + ch)) * HW2;
    float s = bv;
    #pragma unroll
    for (int ky = 0; ky < 4; ky++) {
        int y = oy*4 - 1 + ky;
        if ((unsigned)y >= (unsigned)HWd) continue;
        #pragma unroll
        for (int kx = 0; kx < 4; kx++) {
            int x = ox*4 - 1 + kx;
            if ((unsigned)x >= (unsigned)HWd) continue;
            s += wgt[ky*4+kx] * in[y*HWd + x];
        }
    }
    g_buf4[idx] = s;
}

// ---------------- l2 normalize + token-major q/k (temp folded into q) --------
__global__ void __launch_bounds__(256) norm_qk(float* __restrict__ kout,
                                               const float* __restrict__ temp)
{
    int token = blockIdx.x, b = blockIdx.y, d = threadIdx.x;
    float qv = g_buf4[((long)b*512 + d)       * Ntok + token];
    float kv = g_buf4[((long)b*512 + 256 + d) * Ntok + token];
    __shared__ float red[256];
    __shared__ float qinv_s, kinv_s;
    red[d] = qv*qv; __syncthreads();
    for (int s = 128; s > 0; s >>= 1) { if (d < s) red[d] += red[d+s]; __syncthreads(); }
    if (d == 0) qinv_s = (*temp) / fmaxf(sqrtf(red[0]), 1e-12f);
    __syncthreads();
    red[d] = kv*kv; __syncthreads();
    for (int s = 128; s > 0; s >>= 1) { if (d < s) red[d] += red[d+s]; __syncthreads(); }
    if (d == 0) kinv_s = 1.f / fmaxf(sqrtf(red[0]), 1e-12f);
    __syncthreads();
    g_qtok[((long)b*Ntok + token) * D2 + d] = qv * qinv_s;
    kout  [((long)(b*2 + 1)*Ntok + token) * D2 + d] = kv * kinv_s;
}

// ---------------- build v_new (strided-window permute) into d_out ------------
__global__ void build_vnew(float* __restrict__ vout)
{
    int idx = blockIdx.x * 256 + threadIdx.x;
    if (idx >= BATCH*Ntok*VDdim) return;
    int vd    = idx % VDdim;
    int token = (idx / VDdim) % Ntok;
    int b     = idx / (Ntok*VDdim);
    int c  = vd & 127;
    int p2 = (vd >> 7) & 3;
    int p1 = vd >> 9;
    int hi = token / HGd, wi = token % HGd;
    float val = g_buf2[((long)(b*384 + 256 + c)) * HW2 + (p1*HGd + hi) * HWd + (p2*HGd + wi)];
    vout[((long)(b*2 + 1)*Ntok + token) * VDdim + vd] = val;
}

// ---------------- top-k + local-mask sparse softmax + sparse AV --------------
__global__ void __launch_bounds__(256) sparse_attn_av(
    const float* __restrict__ v_cached, const float* __restrict__ vout)
{
    int n = blockIdx.x, f = blockIdx.y, b = blockIdx.z;
    const float* arow = g_attn + ((long)(b*NFtot + f) * Ntok + n) * Ntok;
    int tid = threadIdx.x;

    // pass 1: per-thread top-5
    float t5[5] = {-INFINITY,-INFINITY,-INFINITY,-INFINITY,-INFINITY};
    for (int m = tid; m < Ntok; m += 256) {
        float v = arow[m];
        if (v > t5[4]) {
            t5[4] = v;
            #pragma unroll
            for (int i = 4; i > 0; i--)
                if (t5[i] > t5[i-1]) { float tmp = t5[i-1]; t5[i-1] = t5[i]; t5[i] = tmp; }
        }
    }
    __shared__ float cand[256*5];
    __shared__ float red[256];
    #pragma unroll
    for (int i = 0; i < 5; i++) cand[tid*5 + i] = t5[i];
    __syncthreads();

    // 5 rounds of max-with-exclusion -> kth largest
    float thr = INFINITY;
    for (int r = 0; r < 5; r++) {
        float lm = -INFINITY;
        #pragma unroll
        for (int i = 0; i < 5; i++) {
            float v = cand[tid*5 + i];
            if (v < thr && v > lm) lm = v;
        }
        red[tid] = lm; __syncthreads();
        for (int s = 128; s > 0; s >>= 1) { if (tid < s) red[tid] = fmaxf(red[tid], red[tid+s]); __syncthreads(); }
        thr = red[0];
        __syncthreads();
    }
    float kth = thr;

    // pass 2: collect nonzero entries of attn*(1[>=kth] + 1[local])
    __shared__ int   nnz;
    __shared__ int   sidx[LISTCAP];
    __shared__ float sval[LISTCAP];
    if (tid == 0) nnz = 0;
    __syncthreads();
    int ny = n / HGd, nx = n % HGd;
    for (int m = tid; m < Ntok; m += 256) {
        float a = arow[m];
        float coef = (a >= kth) ? 1.f : 0.f;
        int my = m / HGd, mx = m % HGd;
        if (abs(ny - my) + abs(nx - mx) <= 4) coef += 1.f;
        float v = a * coef;
        if (v != 0.f) {
            int pos = atomicAdd(&nnz, 1);
            if (pos < LISTCAP) { sidx[pos] = m; sval[pos] = v; }
        }
    }
    __syncthreads();
    int cnt = min(nnz, LISTCAP);

    // softmax over the sparse list
    __shared__ float smax, ssum;
    if (tid == 0) {
        float mx = -INFINITY;
        for (int e = 0; e < cnt; e++) mx = fmaxf(mx, sval[e]);
        smax = mx;
    }
    __syncthreads();
    if (tid < cnt) sval[tid] = expf(sval[tid] - smax);
    __syncthreads();
    if (tid == 0) {
        float s = 0.f;
        for (int e = 0; e < cnt; e++) s += sval[e];
        ssum = s;
    }
    __syncthreads();
    float inv = 1.f / ssum;

    // sparse AV: each thread owns 8 contiguous vd dims
    const float* vbase = (f < 2) ? (v_cached + ((long)(b*2 + f)) * Ntok * VDdim)
                                 : (vout     + ((long)(b*2 + 1)) * Ntok * VDdim);
    float* orow = g_otok + ((long)(b*NFtot + f) * Ntok + n) * VDdim;
    int d0 = tid * 8;
    float acc[8] = {};
    int e = 0;
    for (; e + 2 <= cnt; e += 2) {
        float w0 = sval[e]   * inv;
        float w1 = sval[e+1] * inv;
        const float* vr0 = vbase + (long)sidx[e]   * VDdim + d0;
        const float* vr1 = vbase + (long)sidx[e+1] * VDdim + d0;
        float4 a0 = *(const float4*)vr0;
        float4 a1 = *(const float4*)(vr0 + 4);
        float4 c0 = *(const float4*)vr1;
        float4 c1 = *(const float4*)(vr1 + 4);
        acc[0] += w0*a0.x + w1*c0.x; acc[1] += w0*a0.y + w1*c0.y;
        acc[2] += w0*a0.z + w1*c0.z; acc[3] += w0*a0.w + w1*c0.w;
        acc[4] += w0*a1.x + w1*c1.x; acc[5] += w0*a1.y + w1*c1.y;
        acc[6] += w0*a1.z + w1*c1.z; acc[7] += w0*a1.w + w1*c1.w;
    }
    for (; e < cnt; e++) {
        float w = sval[e] * inv;
        const float* vr = vbase + (long)sidx[e] * VDdim + d0;
        float4 v0 = *(const float4*)vr;
        float4 v1 = *(const float4*)(vr + 4);
        acc[0] += w*v0.x; acc[1] += w*v0.y; acc[2] += w*v0.z; acc[3] += w*v0.w;
        acc[4] += w*v1.x; acc[5] += w*v1.y; acc[6] += w*v1.z; acc[7] += w*v1.w;
    }
    float4 o0 = {acc[0],acc[1],acc[2],acc[3]};
    float4 o1 = {acc[4],acc[5],acc[6],acc[7]};
    *reinterpret_cast<float4*>(orow + d0)     = o0;
    *reinterpret_cast<float4*>(orow + d0 + 4) = o1;
}

// ---------------------------------- launch -----------------------------------
extern "C" void kernel_launch(void* const* d_in, const int* in_sizes, int n_in,
                              void* d_out, int out_size)
{
    (void)in_sizes; (void)n_in; (void)out_size;
    const float* x         = (const float*)d_in[0];
    const float* k_cached  = (const float*)d_in[1];
    const float* v_cached  = (const float*)d_in[2];
    const float* temperature = (const float*)d_in[3];
    const float* qk_w  = (const float*)d_in[4],  *qk_b  = (const float*)d_in[5];
    const float* qk_dw_w = (const float*)d_in[6], *qk_dw_b = (const float*)d_in[7];
    const float* v_w   = (const float*)d_in[8],  *v_b   = (const float*)d_in[9];
    const float* v_dw_w = (const float*)d_in[10], *v_dw_b = (const float*)d_in[11];
    const float* k2_w  = (const float*)d_in[12], *k2_b  = (const float*)d_in[13];
    const float* k2_dw_w = (const float*)d_in[14], *k2_dw_b = (const float*)d_in[15];
    const float* q2_w  = (const float*)d_in[16], *q2_b  = (const float*)d_in[17];
    const float* q2_dw_w = (const float*)d_in[18], *q2_dw_b = (const float*)d_in[19];
    const float* proj_w = (const float*)d_in[20], *proj_b = (const float*)d_in[21];

    float* out = (float*)d_out;
    const long OUT_K = (long)BATCH * NFtot * 128 * HW2;           // 28,311,552
    const long OUT_V = OUT_K + (long)BATCH * 2 * Ntok * D2;       // +2,359,296
    float* kout = out + OUT_K;
    float* vout = out + OUT_V;

    void* p;
    cudaGetSymbolAddress(&p, g_buf1); float* buf1 = (float*)p;
    cudaGetSymbolAddress(&p, g_buf2); float* buf2 = (float*)p;
    cudaGetSymbolAddress(&p, g_buf3); float* buf3 = (float*)p;

    dim3 blk(256);

    // stage A: 1x1 convs from x (qk: 256ch, v: 128ch)
    sgemm_conv<<<dim3(288,2,BATCH), blk>>>(qk_w, x, qk_b, buf1,
                                           128, (long)128*HW2, (long)384*HW2, HW2, HW2);
    sgemm_conv<<<dim3(288,1,BATCH), blk>>>(v_w, x, v_b, buf1 + (long)256*HW2,
                                           128, (long)128*HW2, (long)384*HW2, HW2, HW2);
    // stage B: depthwise 3x3 pad1 on all 384 channels
    dw3x3<<<(BATCH*384*HW2 + 255)/256, blk>>>(qk_dw_w, qk_dw_b, v_dw_w, v_dw_b);
    // stage C: 1x1 convs q2 (from q half) and k2 (from k half)
    sgemm_conv<<<dim3(288,2,BATCH), blk>>>(q2_w, buf2, q2_b, buf3,
                                           128, (long)384*HW2, (long)512*HW2, HW2, HW2);
    sgemm_conv<<<dim3(288,2,BATCH), blk>>>(k2_w, buf2 + (long)128*HW2, k2_b, buf3 + (long)256*HW2,
                                           128, (long)384*HW2, (long)512*HW2, HW2, HW2);
    // stage D: depthwise 4x4 stride4 pad1 -> 48x48 token grid
    dw4x4<<<(BATCH*512*Ntok + 255)/256, blk>>>(q2_dw_w, q2_dw_b, k2_dw_w, k2_dw_b);
    // stage E: l2-normalize q/k (temperature folded into q); k_new into d_out
    norm_qk<<<dim3(Ntok, BATCH), blk>>>(kout, temperature);
    // stage F: v_new window permute straight into d_out
    build_vnew<<<(BATCH*Ntok*VDdim + 255)/256, blk>>>(vout);
    // cached slices -> output slots f'=0
    for (int b = 0; b < BATCH; b++) {
        cudaMemcpyAsync(kout + (long)(b*2)*Ntok*D2,
                        k_cached + (long)(b*2+1)*Ntok*D2,
                        (size_t)Ntok*D2*sizeof(float), cudaMemcpyDeviceToDevice, 0);
        cudaMemcpyAsync(vout + (long)(b*2)*Ntok*VDdim,
                        v_cached + (long)(b*2+1)*Ntok*VDdim,
                        (size_t)Ntok*VDdim*sizeof(float), cudaMemcpyDeviceToDevice, 0);
    }
    // stage G: attention logits (6 GEMMs via grid.z)
    attn_gemm2<<<dim3(18,18,BATCH*NFtot), blk>>>(k_cached, kout);
    // stage H: top-k + local mask sparse softmax + sparse AV
    sparse_attn_av<<<dim3(Ntok, NFtot, BATCH), blk>>>(v_cached, vout);
    // stage I: proj 1x1 with fused de-permute, writes final out
    proj_gemm2<<<dim3(288,1,BATCH*NFtot), blk>>>(proj_w, proj_b, out);
}